// round 5
// baseline (speedup 1.0000x reference)
#include <cuda_runtime.h>
#include <cstdint>

// Problem constants
#define B    32
#define H    768
#define W    768
#define IMG  (H * W)               // 589824
#define NPIX (B * IMG)             // 18874368
#define RSM_K 35

// Row chunking: 16 chunks of 48 rows (+18/+17 halo rows read)
#define CHUNKS 16
#define CHUNK_ROWS (H / CHUNKS)    // 48
#define PAD 20
// Inner extent of the prefix row, rounded to a multiple of 4 so BOTH rows are
// 16-byte aligned (805 -> 808). 805 caused the R4 misaligned-address crash.
#define PROW 808

// ---------------------------------------------------------------------------
// Fully fused kernel.
// Block: 192 threads, each owns 4 adjacent columns (x0 = 4*tid), covering the
// full row width W=768. Vertically walks CHUNK_ROWS output rows.
//
// Per column, a 36-bit shift register 'win' holds recent mask bits
// (bit k = row t-k after shifting in row t). The fused vertical stat
//   v = cnt35 << 16 | cnt31      (35-row window count, 31-row window count)
// is updated incrementally with 4 taps. Horizontal windows come from a
// block-wide fused prefix sum of v (2 rows per barrier pair).
// ---------------------------------------------------------------------------
__global__ __launch_bounds__(192) void fused_kernel(const float* __restrict__ masks,
                                                    float* __restrict__ out_rsm,
                                                    float* __restrict__ out_pfm) {
    __shared__ __align__(16) uint32_t sPp[2][PROW];  // padded fused prefix, 2 rows
    __shared__ uint32_t sWT[2][8];                   // per-warp totals, 2 rows

    const int tid   = threadIdx.x;
    const int lane  = tid & 31;
    const int wid   = tid >> 5;
    const int chunk = blockIdx.x & (CHUNKS - 1);
    const int b     = blockIdx.x >> 4;          // log2(CHUNKS)=4
    const int x0    = tid * 4;
    const int r0    = chunk * CHUNK_ROWS;

    const float* ibase = masks + (size_t)b * IMG + x0;

    // Left pad zeros (written once; first read happens after a later barrier)
    if (tid < PAD) { sPp[0][tid] = 0; sPp[1][tid] = 0; }

    uint64_t win[4] = {0, 0, 0, 0};

    // ---- Prologue: shift in rows r0-18 .. r0+16 (35 rows), batches of 7 ----
    #pragma unroll 1
    for (int pb = 0; pb < 35; pb += 7) {
        float4 f[7];
        #pragma unroll
        for (int i = 0; i < 7; ++i) {
            const int t = r0 - 18 + pb + i;     // t <= r0+16 <= 736 < H always
            f[i] = make_float4(0.f, 0.f, 0.f, 0.f);
            if (t >= 0) f[i] = *(const float4*)(ibase + (size_t)t * W);
        }
        #pragma unroll
        for (int i = 0; i < 7; ++i) {
            win[0] = (win[0] << 1) | (uint64_t)(f[i].x > 0.5f);
            win[1] = (win[1] << 1) | (uint64_t)(f[i].y > 0.5f);
            win[2] = (win[2] << 1) | (uint64_t)(f[i].z > 0.5f);
            win[3] = (win[3] << 1) | (uint64_t)(f[i].w > 0.5f);
        }
    }

    // Seed fused v at y = r0-1:
    //   cnt35(y) = popc rows y-17..y+17 = bits 0..34
    //   cnt31(y) = popc rows y-15..y+15 = bits 2..32
    const uint64_t M35 = (1ULL << 35) - 1;
    const uint64_t M31 = (1ULL << 31) - 1;
    uint32_t v[4];
    #pragma unroll
    for (int c = 0; c < 4; ++c) {
        uint32_t V35 = (uint32_t)__popcll(win[c] & M35);
        uint32_t V31 = (uint32_t)__popcll((win[c] >> 2) & M31);
        v[c] = (V35 << 16) | V31;
    }

    const float inv = 1.0f / (float)(RSM_K * RSM_K);

    // ---- Main loop: 4 rows per load batch, 2 rows per scan/barrier pair ----
    #pragma unroll 1
    for (int yb = 0; yb < CHUNK_ROWS; yb += 4) {
        float4 f[4];
        #pragma unroll
        for (int i = 0; i < 4; ++i) {
            const int t = r0 + yb + i + 17;
            f[i] = make_float4(0.f, 0.f, 0.f, 0.f);
            if (t < H) f[i] = *(const float4*)(ibase + (size_t)t * W);
        }

        #pragma unroll
        for (int half = 0; half < 2; ++half) {
            uint32_t va[2][4];      // snapshot of v per sub-row
            uint32_t cen[2][4];     // center mask bits
            #pragma unroll
            for (int s = 0; s < 2; ++s) {
                const int i = half * 2 + s;
                uint32_t m[4];
                m[0] = (f[i].x > 0.5f);
                m[1] = (f[i].y > 0.5f);
                m[2] = (f[i].z > 0.5f);
                m[3] = (f[i].w > 0.5f);
                #pragma unroll
                for (int c = 0; c < 4; ++c) {
                    win[c] = (win[c] << 1) | (uint64_t)m[c];
                    const uint32_t lo = (uint32_t)win[c];
                    const uint32_t hi = (uint32_t)(win[c] >> 32);
                    const uint32_t b35 = (hi >> 3) & 1u;   // row y-18 (leaves 35-window)
                    const uint32_t b33 = (hi >> 1) & 1u;   // row y-16 (leaves 31-window)
                    const uint32_t b2  = (lo >> 2) & 1u;   // row y+15 (enters 31-window)
                    cen[s][c] = (lo >> 17) & 1u;           // row y
                    v[c] += (m[c] - b35) * 65536u + (b2 - b33);
                    va[s][c] = v[c];
                }
            }

            // Two independent block scans (same barriers)
            uint32_t p[2][4], s3[2], sc[2];
            #pragma unroll
            for (int s = 0; s < 2; ++s) {
                p[s][0] = va[s][0];
                p[s][1] = p[s][0] + va[s][1];
                p[s][2] = p[s][1] + va[s][2];
                p[s][3] = p[s][2] + va[s][3];
                s3[s] = p[s][3];
                uint32_t x = s3[s];
                #pragma unroll
                for (int d = 1; d < 32; d <<= 1) {
                    uint32_t y = __shfl_up_sync(0xFFFFFFFFu, x, d);
                    if (lane >= d) x += y;
                }
                sc[s] = x;
                if (lane == 31) sWT[s][wid] = x;
            }
            __syncthreads();

            #pragma unroll
            for (int s = 0; s < 2; ++s) {
                // Redundant 6-element cross-warp scan in every warp (no 3rd barrier)
                uint32_t tw = (lane < 6) ? sWT[s][lane] : 0u;
                #pragma unroll
                for (int d = 1; d < 8; d <<= 1) {
                    uint32_t y = __shfl_up_sync(0xFFFFFFFFu, tw, d);
                    if (lane >= d) tw += y;
                }
                const uint32_t tot = __shfl_sync(0xFFFFFFFFu, tw, 5);
                const uint32_t exw = __shfl_sync(0xFFFFFFFFu, tw, (wid > 0) ? (wid - 1) : 0);
                const uint32_t excl = (sc[s] - s3[s]) + ((wid > 0) ? exw : 0u);

                uint4 q;
                q.x = excl + p[s][0];
                q.y = excl + p[s][1];
                q.z = excl + p[s][2];
                q.w = excl + p[s][3];
                *(uint4*)&sPp[s][PAD + x0] = q;
                if (tid < 17) sPp[s][PAD + W + tid] = tot;  // right pad = row total
            }
            __syncthreads();

            // Emit 2 rows
            #pragma unroll
            for (int s = 0; s < 2; ++s) {
                const int y = r0 + yb + half * 2 + s;

                // Window reads (indices pre-shifted by PAD=20):
                //   lo35_j = sPp[x0+j+2], lo31_j = sPp[x0+j+4]
                //   hi31_j = sPp[x0+j+35], hi35_j = sPp[x0+j+37]
                const uint2  A01  = *(const uint2*)&sPp[s][x0 + 2];
                const uint4  A25  = *(const uint4*)&sPp[s][x0 + 4];
                const uint32_t c35 = sPp[s][x0 + 35];
                const uint4  B69  = *(const uint4*)&sPp[s][x0 + 36];
                const uint32_t c40 = sPp[s][x0 + 40];

                // hi - lo: no cross-field borrow (both fields monotone)
                const uint32_t d35_0 = B69.y - A01.x;
                const uint32_t d35_1 = B69.z - A01.y;
                const uint32_t d35_2 = B69.w - A25.x;
                const uint32_t d35_3 = c40   - A25.y;

                const uint32_t f31_0 = (c35   - A25.x) & 0xFFFFu;
                const uint32_t f31_1 = (B69.x - A25.y) & 0xFFFFu;
                const uint32_t f31_2 = (B69.y - A25.z) & 0xFFFFu;
                const uint32_t f31_3 = (B69.z - A25.w) & 0xFFFFu;

                float4 rsm4;
                rsm4.x = (float)(d35_0 >> 16) * inv;
                rsm4.y = (float)(d35_1 >> 16) * inv;
                rsm4.z = (float)(d35_2 >> 16) * inv;
                rsm4.w = (float)(d35_3 >> 16) * inv;

                // pfm = center ? 1 : (any31 ? 0 : 2) == center + 2*(f31==0)
                float4 pfm4;
                pfm4.x = (float)(cen[s][0] + ((f31_0 == 0u) ? 2u : 0u));
                pfm4.y = (float)(cen[s][1] + ((f31_1 == 0u) ? 2u : 0u));
                pfm4.z = (float)(cen[s][2] + ((f31_2 == 0u) ? 2u : 0u));
                pfm4.w = (float)(cen[s][3] + ((f31_3 == 0u) ? 2u : 0u));

                const size_t o = (size_t)b * IMG + (size_t)y * W + x0;
                *(float4*)(out_rsm + o) = rsm4;
                *(float4*)(out_pfm + o) = pfm4;
            }
        }
    }
}

// ---------------------------------------------------------------------------
extern "C" void kernel_launch(void* const* d_in, const int* in_sizes, int n_in,
                              void* d_out, int out_size) {
    const float* masks = (const float*)d_in[0];
    float* out = (float*)d_out;

    fused_kernel<<<B * CHUNKS, 192>>>(masks, out, out + NPIX);
}

// round 6
// speedup vs baseline: 1.0160x; 1.0160x over previous
#include <cuda_runtime.h>
#include <cstdint>

// Problem constants
#define B    32
#define H    768
#define W    768
#define IMG  (H * W)               // 589824
#define NPIX (B * IMG)             // 18874368
#define RSM_K 35

// Row chunking: 16 chunks of 48 rows (+18/+17 halo rows read; halo re-reads
// are L2 hits since the whole input fits in L2)
#define CHUNKS 16
#define CHUNK_ROWS (H / CHUNKS)    // 48
#define PAD 20
// Inner extent of a prefix row, padded to multiple of 4 words (805 -> 808)
#define PROW 808

// ---------------------------------------------------------------------------
// Fully fused kernel. 384 threads/block, 2 adjacent columns per thread
// (x0 = 2*tid), full row width. Walks CHUNK_ROWS output rows, 4 rows per
// barrier pair.
//
// Per column, a 36-bit shift register 'win' holds recent mask bits
// (bit k = row t-k after shifting in row t). Fused vertical stat
//   v = cnt35 << 16 | cnt31
// updated incrementally with 4 single-bit taps. Horizontal windows via a
// block-wide fused prefix sum per row.
// ---------------------------------------------------------------------------
__global__ __launch_bounds__(384) void fused_kernel(const float* __restrict__ masks,
                                                    float* __restrict__ out_rsm,
                                                    float* __restrict__ out_pfm) {
    __shared__ __align__(16) uint32_t sPp[4][PROW];  // padded fused prefix, 4 rows
    __shared__ uint32_t sWT[4][12];                  // per-warp totals, 4 rows

    const int tid   = threadIdx.x;
    const int lane  = tid & 31;
    const int wid   = tid >> 5;                 // 0..11
    const int chunk = blockIdx.x & (CHUNKS - 1);
    const int b     = blockIdx.x >> 4;          // log2(CHUNKS)=4
    const int x0    = tid * 2;
    const int r0    = chunk * CHUNK_ROWS;

    const float* ibase = masks + (size_t)b * IMG + x0;

    // Left pad zeros (first read happens after two later barriers)
    if (tid < PAD) {
        sPp[0][tid] = 0; sPp[1][tid] = 0; sPp[2][tid] = 0; sPp[3][tid] = 0;
    }

    uint64_t win0 = 0, win1 = 0;

    // ---- Prologue: shift in rows r0-18 .. r0+16 (35 rows), batches of 7 ----
    #pragma unroll 1
    for (int pb = 0; pb < 35; pb += 7) {
        float2 f[7];
        #pragma unroll
        for (int i = 0; i < 7; ++i) {
            const int t = r0 - 18 + pb + i;     // t <= 736 < H always
            f[i] = make_float2(0.f, 0.f);
            if (t >= 0) f[i] = *(const float2*)(ibase + (size_t)t * W);
        }
        #pragma unroll
        for (int i = 0; i < 7; ++i) {
            win0 = (win0 << 1) | (uint64_t)(f[i].x > 0.5f);
            win1 = (win1 << 1) | (uint64_t)(f[i].y > 0.5f);
        }
    }

    // Seed fused v at y = r0-1:
    //   cnt35 = popc bits 0..34 ; cnt31 = popc bits 2..32
    const uint64_t M35 = (1ULL << 35) - 1;
    const uint64_t M31 = (1ULL << 31) - 1;
    uint32_t v0 = ((uint32_t)__popcll(win0 & M35) << 16) |
                   (uint32_t)__popcll((win0 >> 2) & M31);
    uint32_t v1 = ((uint32_t)__popcll(win1 & M35) << 16) |
                   (uint32_t)__popcll((win1 >> 2) & M31);

    const float inv = 1.0f / (float)(RSM_K * RSM_K);

    // ---- Main loop: 4 rows per load batch and per barrier pair ----
    #pragma unroll 1
    for (int yb = 0; yb < CHUNK_ROWS; yb += 4) {
        float2 f[4];
        #pragma unroll
        for (int i = 0; i < 4; ++i) {
            const int t = r0 + yb + i + 17;
            f[i] = make_float2(0.f, 0.f);
            if (t < H) f[i] = *(const float2*)(ibase + (size_t)t * W);
        }

        // Vertical updates for 4 rows; snapshot fused values
        uint32_t va[4][2];
        uint32_t cenpack = 0;                    // bit (i*2+c) = center bit
        #pragma unroll
        for (int i = 0; i < 4; ++i) {
            const uint32_t m0 = (f[i].x > 0.5f);
            const uint32_t m1 = (f[i].y > 0.5f);

            win0 = (win0 << 1) | (uint64_t)m0;
            {
                const uint32_t lo = (uint32_t)win0;
                const uint32_t hi = (uint32_t)(win0 >> 32);
                v0 += (m0 - ((hi >> 3) & 1u)) * 65536u
                    + (((lo >> 2) & 1u) - ((hi >> 1) & 1u));
                cenpack |= ((lo >> 17) & 1u) << (i * 2);
            }
            va[i][0] = v0;

            win1 = (win1 << 1) | (uint64_t)m1;
            {
                const uint32_t lo = (uint32_t)win1;
                const uint32_t hi = (uint32_t)(win1 >> 32);
                v1 += (m1 - ((hi >> 3) & 1u)) * 65536u
                    + (((lo >> 2) & 1u) - ((hi >> 1) & 1u));
                cenpack |= ((lo >> 17) & 1u) << (i * 2 + 1);
            }
            va[i][1] = v1;
        }

        // 4 independent warp scans (ILP), then one barrier
        uint32_t pr1[4], pr0[4], sc[4];
        #pragma unroll
        for (int i = 0; i < 4; ++i) {
            pr0[i] = va[i][0];
            pr1[i] = pr0[i] + va[i][1];
            uint32_t x = pr1[i];
            #pragma unroll
            for (int d = 1; d < 32; d <<= 1) {
                uint32_t y = __shfl_up_sync(0xFFFFFFFFu, x, d);
                if (lane >= d) x += y;
            }
            sc[i] = x;
            if (lane == 31) sWT[i][wid] = x;
        }
        __syncthreads();

        #pragma unroll
        for (int i = 0; i < 4; ++i) {
            // Redundant 12-element cross-warp scan in every warp
            uint32_t tw = (lane < 12) ? sWT[i][lane] : 0u;
            #pragma unroll
            for (int d = 1; d < 16; d <<= 1) {
                uint32_t y = __shfl_up_sync(0xFFFFFFFFu, tw, d);
                if (lane >= d) tw += y;
            }
            const uint32_t tot = __shfl_sync(0xFFFFFFFFu, tw, 11);
            const uint32_t exw = __shfl_sync(0xFFFFFFFFu, tw, (wid > 0) ? (wid - 1) : 0);
            const uint32_t excl = (sc[i] - pr1[i]) + ((wid > 0) ? exw : 0u);

            uint2 q;
            q.x = excl + pr0[i];
            q.y = excl + pr1[i];
            *(uint2*)&sPp[i][PAD + x0] = q;
            if (tid < 17) sPp[i][PAD + W + tid] = tot;   // right pad = row total
        }
        __syncthreads();

        // Emit 4 rows
        #pragma unroll
        for (int i = 0; i < 4; ++i) {
            const int y = r0 + yb + i;

            // Window reads (indices pre-shifted by PAD=20); for x = x0+j:
            //   lo35 = P[x-18] -> sPp[x0+j+2]
            //   lo31 = P[x-16] -> sPp[x0+j+4]
            //   hi31 = P[x+15] -> sPp[x0+j+35]
            //   hi35 = P[x+17] -> sPp[x0+j+37]
            const uint2 lo35 = *(const uint2*)&sPp[i][x0 + 2];
            const uint2 lo31 = *(const uint2*)&sPp[i][x0 + 4];
            const uint32_t h31_0 = sPp[i][x0 + 35];
            const uint2 hmid = *(const uint2*)&sPp[i][x0 + 36]; // {h31_1, h35_0}
            const uint32_t h35_1 = sPp[i][x0 + 38];

            // hi - lo: no cross-field borrow (both fields monotone)
            const uint32_t d35_0 = hmid.y - lo35.x;
            const uint32_t d35_1 = h35_1 - lo35.y;
            const uint32_t f31_0 = (h31_0  - lo31.x) & 0xFFFFu;
            const uint32_t f31_1 = (hmid.x - lo31.y) & 0xFFFFu;

            float2 rsm2;
            rsm2.x = (float)(d35_0 >> 16) * inv;
            rsm2.y = (float)(d35_1 >> 16) * inv;

            // pfm = center ? 1 : (any31 ? 0 : 2) == center + 2*(f31==0)
            float2 pfm2;
            pfm2.x = (float)(((cenpack >> (i * 2)) & 1u) + ((f31_0 == 0u) ? 2u : 0u));
            pfm2.y = (float)(((cenpack >> (i * 2 + 1)) & 1u) + ((f31_1 == 0u) ? 2u : 0u));

            const size_t o = (size_t)b * IMG + (size_t)y * W + x0;
            *(float2*)(out_rsm + o) = rsm2;
            *(float2*)(out_pfm + o) = pfm2;
        }
    }
}

// ---------------------------------------------------------------------------
extern "C" void kernel_launch(void* const* d_in, const int* in_sizes, int n_in,
                              void* d_out, int out_size) {
    const float* masks = (const float*)d_in[0];
    float* out = (float*)d_out;

    fused_kernel<<<B * CHUNKS, 384>>>(masks, out, out + NPIX);
}